// round 1
// baseline (speedup 1.0000x reference)
#include <cuda_runtime.h>

#define D 128
#define NEG 0.01f
#define NMAX 100000

// Scratch (allocation-free rule: __device__ globals)
__device__ float g_h[NMAX * D];      // h = x @ W (pre-aggregation)
__device__ float g_acc[NMAX * D];    // layer-1 aggregation accumulator
__device__ float g_acc2[NMAX * D];   // layer-2 aggregation accumulator
__device__ float g_dinv[NMAX];       // deg^{-1/2}
__device__ int   g_cnt[NMAX];        // in-degree counts

// ---------------------------------------------------------------------------
// Degree pipeline
// ---------------------------------------------------------------------------
__global__ void k_zero_cnt(int n) {
    int i = blockIdx.x * blockDim.x + threadIdx.x;
    if (i < n) g_cnt[i] = 0;
}

__global__ void k_count(const int* __restrict__ dst, int e) {
    int i = blockIdx.x * blockDim.x + threadIdx.x;
    if (i < e) atomicAdd(&g_cnt[dst[i]], 1);
}

__global__ void k_rsqrt(int n) {
    int i = blockIdx.x * blockDim.x + threadIdx.x;
    if (i < n) g_dinv[i] = rsqrtf((float)g_cnt[i] + 1.0f);
}

// ---------------------------------------------------------------------------
// GEMM: H[n,128] = X'[n,128] @ W[128,128]
//   MODE 0: X' = X                       (layer 1)
//   MODE 1: X' = leakyrelu(X + bias_in)  (layer 2: fuses layer-1 epilogue)
// Epilogue also writes ACC = H * dinv^2  (self-loop term of aggregation).
// BM=64, BN=128, BK=16, 256 threads, each computes 8x4 outputs.
// ---------------------------------------------------------------------------
template <int MODE>
__global__ void __launch_bounds__(256)
k_gemm(const float* __restrict__ X, const float* __restrict__ W,
       const float* __restrict__ bias_in,
       float* __restrict__ H, float* __restrict__ ACC, int n)
{
    __shared__ float As[16][65];   // [k][row], padded
    __shared__ float Bs[16][128];  // [k][col]

    const int t  = threadIdx.x;
    const int tx = t & 31;         // 32 col-groups (4 cols each)
    const int ty = t >> 5;         // 8 row-groups (8 rows each)
    const int row0 = blockIdx.x * 64;

    float acc[8][4];
#pragma unroll
    for (int i = 0; i < 8; i++)
#pragma unroll
        for (int j = 0; j < 4; j++) acc[i][j] = 0.0f;

    for (int kt = 0; kt < D; kt += 16) {
        // --- load A tile: 64 rows x 16 k, one float4 per thread
        {
            int ar = t >> 2;             // 0..63
            int ac = (t & 3) << 2;       // 0,4,8,12
            int r = row0 + ar;
            float4 v = make_float4(0.f, 0.f, 0.f, 0.f);
            if (r < n) v = *(const float4*)&X[(size_t)r * D + kt + ac];
            if (MODE == 1) {
                float4 b = *(const float4*)&bias_in[kt + ac];
                v.x += b.x; v.y += b.y; v.z += b.z; v.w += b.w;
                v.x = fmaxf(v.x, NEG * v.x);
                v.y = fmaxf(v.y, NEG * v.y);
                v.z = fmaxf(v.z, NEG * v.z);
                v.w = fmaxf(v.w, NEG * v.w);
            }
            As[ac + 0][ar] = v.x;
            As[ac + 1][ar] = v.y;
            As[ac + 2][ar] = v.z;
            As[ac + 3][ar] = v.w;
        }
        // --- load B tile: 16 k x 128 cols, two float4 per thread
#pragma unroll
        for (int q = 0; q < 2; q++) {
            int idx = t + q * 256;       // 0..511
            int br = idx >> 5;           // 0..15
            int bc = (idx & 31) << 2;    // 0..124
            *(float4*)&Bs[br][bc] = *(const float4*)&W[(size_t)(kt + br) * D + bc];
        }
        __syncthreads();

#pragma unroll
        for (int kk = 0; kk < 16; kk++) {
            float4 bb = *(const float4*)&Bs[kk][tx << 2];
            float a_[8];
#pragma unroll
            for (int i = 0; i < 8; i++) a_[i] = As[kk][(ty << 3) + i];
#pragma unroll
            for (int i = 0; i < 8; i++) {
                acc[i][0] = fmaf(a_[i], bb.x, acc[i][0]);
                acc[i][1] = fmaf(a_[i], bb.y, acc[i][1]);
                acc[i][2] = fmaf(a_[i], bb.z, acc[i][2]);
                acc[i][3] = fmaf(a_[i], bb.w, acc[i][3]);
            }
        }
        __syncthreads();
    }

    // --- epilogue: write H and ACC = H * dinv^2
#pragma unroll
    for (int i = 0; i < 8; i++) {
        int r = row0 + (ty << 3) + i;
        if (r < n) {
            float di = g_dinv[r];
            float d2 = di * di;
            float4 hv = make_float4(acc[i][0], acc[i][1], acc[i][2], acc[i][3]);
            *(float4*)&H[(size_t)r * D + (tx << 2)] = hv;
            float4 av = make_float4(hv.x * d2, hv.y * d2, hv.z * d2, hv.w * d2);
            *(float4*)&ACC[(size_t)r * D + (tx << 2)] = av;
        }
    }
}

// ---------------------------------------------------------------------------
// Scatter: for each edge, ACC[dst] += H[src] * dinv[src]*dinv[dst]
// One warp per edge; lane handles one float4 (32*16B = 512B = full row).
// ---------------------------------------------------------------------------
__global__ void __launch_bounds__(256)
k_scatter(const float* __restrict__ H, float* __restrict__ ACC,
          const int* __restrict__ src, const int* __restrict__ dst, int e)
{
    int w    = (blockIdx.x * blockDim.x + threadIdx.x) >> 5;
    int lane = threadIdx.x & 31;
    if (w >= e) return;
    int s = __ldg(&src[w]);
    int d = __ldg(&dst[w]);
    float coef = g_dinv[s] * g_dinv[d];
    float4 v = *(const float4*)&H[(size_t)s * D + (lane << 2)];
    v.x *= coef; v.y *= coef; v.z *= coef; v.w *= coef;
    float* p = &ACC[(size_t)d * D + (lane << 2)];
    asm volatile("red.global.add.v4.f32 [%0], {%1, %2, %3, %4};"
                 :: "l"(p), "f"(v.x), "f"(v.y), "f"(v.z), "f"(v.w)
                 : "memory");
}

// ---------------------------------------------------------------------------
// Final epilogue: out = leakyrelu(acc2 + b2)
// ---------------------------------------------------------------------------
__global__ void k_final(const float* __restrict__ ACC, const float* __restrict__ bias,
                        float* __restrict__ out, int n)
{
    int i = blockIdx.x * blockDim.x + threadIdx.x;   // over n*32 float4s
    if (i >= n * (D / 4)) return;
    float4 v = *(const float4*)&ACC[(size_t)i * 4];
    float4 b = *(const float4*)&bias[(i & 31) * 4];
    v.x += b.x; v.y += b.y; v.z += b.z; v.w += b.w;
    v.x = fmaxf(v.x, NEG * v.x);
    v.y = fmaxf(v.y, NEG * v.y);
    v.z = fmaxf(v.z, NEG * v.z);
    v.w = fmaxf(v.w, NEG * v.w);
    *(float4*)&out[(size_t)i * 4] = v;
}

// ---------------------------------------------------------------------------
extern "C" void kernel_launch(void* const* d_in, const int* in_sizes, int n_in,
                              void* d_out, int out_size)
{
    const float* x  = (const float*)d_in[0];
    const float* W1 = (const float*)d_in[1];
    const float* b1 = (const float*)d_in[2];
    const float* W2 = (const float*)d_in[3];
    const float* b2 = (const float*)d_in[4];
    const int*   ei = (const int*)d_in[5];
    // d_in[6] = batch (unused)

    const int n = in_sizes[0] / D;
    const int e = in_sizes[5] / 2;
    const int* src = ei;
    const int* dst = ei + e;

    float *h, *acc, *acc2;
    cudaGetSymbolAddress((void**)&h,    g_h);
    cudaGetSymbolAddress((void**)&acc,  g_acc);
    cudaGetSymbolAddress((void**)&acc2, g_acc2);

    // degree
    k_zero_cnt<<<(n + 255) / 256, 256>>>(n);
    k_count<<<(e + 255) / 256, 256>>>(dst, e);
    k_rsqrt<<<(n + 255) / 256, 256>>>(n);

    const int gemm_blocks = (n + 63) / 64;
    const long long sc_threads = (long long)e * 32;
    const int sc_blocks = (int)((sc_threads + 255) / 256);

    // layer 1
    k_gemm<0><<<gemm_blocks, 256>>>(x, W1, nullptr, h, acc, n);
    k_scatter<<<sc_blocks, 256>>>(h, acc, src, dst, e);

    // layer 2 (layer-1 bias+leakyrelu fused into A-tile load)
    k_gemm<1><<<gemm_blocks, 256>>>(acc, W2, b1, h, acc2, n);
    k_scatter<<<sc_blocks, 256>>>(h, acc2, src, dst, e);

    // final bias + leakyrelu
    k_final<<<(n * (D / 4) + 255) / 256, 256>>>(acc2, b2, (float*)d_out, n);
}

// round 2
// speedup vs baseline: 1.5762x; 1.5762x over previous
#include <cuda_runtime.h>

#define D 128
#define NEG 0.01f
#define NMAX 100000
#define EMAX 2000000
#define NBMAX 128   // scan blocks: ceil(NMAX/1024) = 98

// Scratch (allocation-free rule: __device__ globals)
__device__ float g_h[NMAX * D];        // h = x @ W (pre-aggregation)
__device__ float g_acc[NMAX * D];      // layer-1 aggregation output
__device__ float g_dinv[NMAX];         // deg^{-1/2}
__device__ int   g_cnt[NMAX];          // in-degree counts
__device__ int   g_rptr[NMAX + 1];     // CSR row pointers (by dst)
__device__ int   g_cursor[NMAX];       // fill cursors
__device__ int   g_partial[NMAX];      // block-local inclusive scan
__device__ int   g_bsum[NBMAX];        // per-block sums
__device__ int   g_boff[NBMAX];        // block offsets
__device__ int   g_col[EMAX];          // CSR column indices (src nodes)

// ---------------------------------------------------------------------------
// Degree + CSR build
// ---------------------------------------------------------------------------
__global__ void k_zero_cnt(int n) {
    int i = blockIdx.x * blockDim.x + threadIdx.x;
    if (i < n) g_cnt[i] = 0;
}

__global__ void k_count(const int* __restrict__ dst, int e) {
    int i = blockIdx.x * blockDim.x + threadIdx.x;
    if (i < e) atomicAdd(&g_cnt[dst[i]], 1);
}

// block-wise inclusive scan of g_cnt (1024 elems per block)
__global__ void __launch_bounds__(1024) k_scan_block(int n) {
    __shared__ int sh[1024];
    int i = blockIdx.x * 1024 + threadIdx.x;
    int v = (i < n) ? g_cnt[i] : 0;
    sh[threadIdx.x] = v;
#pragma unroll
    for (int off = 1; off < 1024; off <<= 1) {
        __syncthreads();
        int t = (threadIdx.x >= off) ? sh[threadIdx.x - off] : 0;
        __syncthreads();
        sh[threadIdx.x] += t;
    }
    if (i < n) g_partial[i] = sh[threadIdx.x];
    if (threadIdx.x == 1023) g_bsum[blockIdx.x] = sh[1023];
}

__global__ void k_scan_sums(int nb) {
    if (threadIdx.x == 0) {
        int s = 0;
        for (int b = 0; b < nb; b++) { int t = g_bsum[b]; g_boff[b] = s; s += t; }
    }
}

// finalize rptr/cursor, compute dinv
__global__ void k_finalize(int n) {
    int i = blockIdx.x * blockDim.x + threadIdx.x;
    if (i >= n) return;
    int incl = g_partial[i] + g_boff[i >> 10];
    g_rptr[i + 1] = incl;
    g_cursor[i] = incl - g_cnt[i];
    if (i == 0) g_rptr[0] = 0;
    g_dinv[i] = rsqrtf((float)g_cnt[i] + 1.0f);
}

__global__ void k_fill(const int* __restrict__ src, const int* __restrict__ dst, int e) {
    int i = blockIdx.x * blockDim.x + threadIdx.x;
    if (i < e) {
        int d = dst[i];
        int pos = atomicAdd(&g_cursor[d], 1);
        g_col[pos] = src[i];
    }
}

// ---------------------------------------------------------------------------
// GEMM: H[n,128] = X'[n,128] @ W[128,128]
//   MODE 0: X' = X
//   MODE 1: X' = leakyrelu(X + bias_in)  (fuses previous layer's epilogue)
// BM=128, BN=128, BK=8, 256 threads, 8x8 outputs per thread.
// ---------------------------------------------------------------------------
template <int MODE>
__global__ void __launch_bounds__(256)
k_gemm(const float* __restrict__ X, const float* __restrict__ W,
       const float* __restrict__ bias_in, float* __restrict__ H, int n)
{
    __shared__ float As[8][132];   // [k][m], padded to kill STS conflicts
    __shared__ float Bs[8][128];   // [k][ncol]

    const int t  = threadIdx.x;
    const int tx = t & 15;         // 16 col-groups (8 cols each)
    const int ty = t >> 4;         // 16 row-groups (8 rows each)
    const int row0 = blockIdx.x * 128;

    float acc[8][8];
#pragma unroll
    for (int i = 0; i < 8; i++)
#pragma unroll
        for (int j = 0; j < 8; j++) acc[i][j] = 0.0f;

    const int ar = t >> 1;           // 0..127
    const int ac = (t & 1) << 2;     // 0 or 4
    const int bk = t >> 5;           // 0..7
    const int bc = (t & 31) << 2;    // 0..124

    for (int kt = 0; kt < D; kt += 8) {
        // A tile: 128 rows x 8 k
        {
            int r = row0 + ar;
            float4 v = make_float4(0.f, 0.f, 0.f, 0.f);
            if (r < n) v = *(const float4*)&X[(size_t)r * D + kt + ac];
            if (MODE == 1) {
                float4 b = *(const float4*)&bias_in[kt + ac];
                v.x += b.x; v.y += b.y; v.z += b.z; v.w += b.w;
                v.x = fmaxf(v.x, NEG * v.x);
                v.y = fmaxf(v.y, NEG * v.y);
                v.z = fmaxf(v.z, NEG * v.z);
                v.w = fmaxf(v.w, NEG * v.w);
            }
            As[ac + 0][ar] = v.x;
            As[ac + 1][ar] = v.y;
            As[ac + 2][ar] = v.z;
            As[ac + 3][ar] = v.w;
        }
        // B tile: 8 k x 128 cols
        *(float4*)&Bs[bk][bc] = *(const float4*)&W[(size_t)(kt + bk) * D + bc];
        __syncthreads();

#pragma unroll
        for (int k = 0; k < 8; k++) {
            float a[8], b[8];
            *(float4*)&a[0] = *(const float4*)&As[k][ty << 3];
            *(float4*)&a[4] = *(const float4*)&As[k][(ty << 3) + 4];
            *(float4*)&b[0] = *(const float4*)&Bs[k][tx << 3];
            *(float4*)&b[4] = *(const float4*)&Bs[k][(tx << 3) + 4];
#pragma unroll
            for (int i = 0; i < 8; i++)
#pragma unroll
                for (int j = 0; j < 8; j++)
                    acc[i][j] = fmaf(a[i], b[j], acc[i][j]);
        }
        __syncthreads();
    }

#pragma unroll
    for (int i = 0; i < 8; i++) {
        int r = row0 + (ty << 3) + i;
        if (r < n) {
            *(float4*)&H[(size_t)r * D + (tx << 3)] =
                make_float4(acc[i][0], acc[i][1], acc[i][2], acc[i][3]);
            *(float4*)&H[(size_t)r * D + (tx << 3) + 4] =
                make_float4(acc[i][4], acc[i][5], acc[i][6], acc[i][7]);
        }
    }
}

// ---------------------------------------------------------------------------
// Aggregation (CSR gather): out[d] = H[d]*dinv[d]^2 + sum_{s in N(d)} H[s]*dinv[s]*dinv[d]
// One warp per dst node; lane owns one float4 column slice.
//   MODE 0: write raw   MODE 1: write leakyrelu(. + bias)
// ---------------------------------------------------------------------------
template <int MODE>
__global__ void __launch_bounds__(256)
k_agg(const float* __restrict__ H, const float* __restrict__ bias,
      float* __restrict__ out, int n)
{
    int node = (blockIdx.x * blockDim.x + threadIdx.x) >> 5;
    int lane = threadIdx.x & 31;
    if (node >= n) return;

    float dd = g_dinv[node];
    float d2 = dd * dd;
    float4 v = *(const float4*)&H[(size_t)node * D + (lane << 2)];
    float4 acc = make_float4(v.x * d2, v.y * d2, v.z * d2, v.w * d2);

    int beg = g_rptr[node], end = g_rptr[node + 1];
    for (int j = beg; j < end; j += 32) {
        int idx = j + lane;
        int s = 0; float c = 0.0f;
        if (idx < end) { s = g_col[idx]; c = g_dinv[s] * dd; }
        int cnt = min(32, end - j);
        for (int t = 0; t < cnt; t++) {
            int   ss = __shfl_sync(0xffffffffu, s, t);
            float cc = __shfl_sync(0xffffffffu, c, t);
            float4 hv = *(const float4*)&H[(size_t)ss * D + (lane << 2)];
            acc.x = fmaf(hv.x, cc, acc.x);
            acc.y = fmaf(hv.y, cc, acc.y);
            acc.z = fmaf(hv.z, cc, acc.z);
            acc.w = fmaf(hv.w, cc, acc.w);
        }
    }

    if (MODE == 1) {
        float4 b = *(const float4*)&bias[lane << 2];
        acc.x += b.x; acc.y += b.y; acc.z += b.z; acc.w += b.w;
        acc.x = fmaxf(acc.x, NEG * acc.x);
        acc.y = fmaxf(acc.y, NEG * acc.y);
        acc.z = fmaxf(acc.z, NEG * acc.z);
        acc.w = fmaxf(acc.w, NEG * acc.w);
    }
    *(float4*)&out[(size_t)node * D + (lane << 2)] = acc;
}

// ---------------------------------------------------------------------------
extern "C" void kernel_launch(void* const* d_in, const int* in_sizes, int n_in,
                              void* d_out, int out_size)
{
    const float* x  = (const float*)d_in[0];
    const float* W1 = (const float*)d_in[1];
    const float* b1 = (const float*)d_in[2];
    const float* W2 = (const float*)d_in[3];
    const float* b2 = (const float*)d_in[4];
    const int*   ei = (const int*)d_in[5];

    const int n = in_sizes[0] / D;
    const int e = in_sizes[5] / 2;
    const int* src = ei;
    const int* dst = ei + e;

    float *h, *acc;
    cudaGetSymbolAddress((void**)&h,   g_h);
    cudaGetSymbolAddress((void**)&acc, g_acc);

    // degree + CSR build
    k_zero_cnt<<<(n + 255) / 256, 256>>>(n);
    k_count<<<(e + 255) / 256, 256>>>(dst, e);
    const int nb = (n + 1023) / 1024;
    k_scan_block<<<nb, 1024>>>(n);
    k_scan_sums<<<1, 32>>>(nb);
    k_finalize<<<(n + 255) / 256, 256>>>(n);
    k_fill<<<(e + 255) / 256, 256>>>(src, dst, e);

    const int gemm_blocks = (n + 127) / 128;
    const int agg_blocks  = (int)(((long long)n * 32 + 255) / 256);

    // layer 1
    k_gemm<0><<<gemm_blocks, 256>>>(x, W1, nullptr, h, n);
    k_agg<0><<<agg_blocks, 256>>>(h, nullptr, acc, n);

    // layer 2 (layer-1 bias+leakyrelu fused into GEMM A-load,
    //          layer-2 bias+leakyrelu fused into aggregation epilogue)
    k_gemm<1><<<gemm_blocks, 256>>>(acc, W2, b1, h, n);
    k_agg<1><<<agg_blocks, 256>>>(h, b2, (float*)d_out, n);
}

// round 3
// speedup vs baseline: 1.9204x; 1.2184x over previous
#include <cuda_runtime.h>
#include <cuda_fp16.h>

#define D 128
#define NEG 0.01f
#define NMAX 100000
#define EMAX 2000000
#define NBMAX 128   // scan blocks: ceil(NMAX/1024) = 98

// Scratch (allocation-free rule: __device__ globals)
__device__ __half2 g_h[NMAX * 64];     // h = x @ W, fp16 (only consumer: agg gather)
__device__ float g_acc[NMAX * D];      // layer-1 aggregation output (fp32)
__device__ float g_dinv[NMAX];         // deg^{-1/2}
__device__ int   g_cnt[NMAX];          // in-degree counts
__device__ int   g_rptr[NMAX + 1];     // CSR row pointers (by dst)
__device__ int   g_cursor[NMAX];       // fill cursors
__device__ int   g_partial[NMAX];      // block-local inclusive scan
__device__ int   g_bsum[NBMAX];        // per-block sums
__device__ int   g_boff[NBMAX];        // block offsets (exclusive)
__device__ int   g_col[EMAX];          // CSR column indices (src nodes)

// ---------------------------------------------------------------------------
// Degree + CSR build
// ---------------------------------------------------------------------------
__global__ void k_zero_cnt(int n) {
    int i = blockIdx.x * blockDim.x + threadIdx.x;
    if (i < n) g_cnt[i] = 0;
}

__global__ void k_count(const int* __restrict__ dst, int e) {
    int i = blockIdx.x * blockDim.x + threadIdx.x;
    if (i < e) atomicAdd(&g_cnt[dst[i]], 1);
}

// block-wise inclusive scan of g_cnt (1024 elems per block)
__global__ void __launch_bounds__(1024) k_scan_block(int n) {
    __shared__ int sh[1024];
    int i = blockIdx.x * 1024 + threadIdx.x;
    int v = (i < n) ? g_cnt[i] : 0;
    sh[threadIdx.x] = v;
#pragma unroll
    for (int off = 1; off < 1024; off <<= 1) {
        __syncthreads();
        int t = (threadIdx.x >= off) ? sh[threadIdx.x - off] : 0;
        __syncthreads();
        sh[threadIdx.x] += t;
    }
    if (i < n) g_partial[i] = sh[threadIdx.x];
    if (threadIdx.x == 1023) g_bsum[blockIdx.x] = sh[1023];
}

// parallel exclusive scan of per-block sums (nb <= 128): one warp, 4 elems/lane
__global__ void k_scan_sums(int nb) {
    int t = threadIdx.x;            // 32 threads
    int b = t * 4;
    int s0 = (b + 0 < nb) ? g_bsum[b + 0] : 0;
    int s1 = (b + 1 < nb) ? g_bsum[b + 1] : 0;
    int s2 = (b + 2 < nb) ? g_bsum[b + 2] : 0;
    int s3 = (b + 3 < nb) ? g_bsum[b + 3] : 0;
    int tot = s0 + s1 + s2 + s3;
    int x = tot;
#pragma unroll
    for (int o = 1; o < 32; o <<= 1) {
        int y = __shfl_up_sync(0xffffffffu, x, o);
        if (t >= o) x += y;
    }
    int excl = x - tot;
    if (b + 0 < nb) g_boff[b + 0] = excl;
    if (b + 1 < nb) g_boff[b + 1] = excl + s0;
    if (b + 2 < nb) g_boff[b + 2] = excl + s0 + s1;
    if (b + 3 < nb) g_boff[b + 3] = excl + s0 + s1 + s2;
}

// finalize rptr/cursor, compute dinv
__global__ void k_finalize(int n) {
    int i = blockIdx.x * blockDim.x + threadIdx.x;
    if (i >= n) return;
    int incl = g_partial[i] + g_boff[i >> 10];
    g_rptr[i + 1] = incl;
    g_cursor[i] = incl - g_cnt[i];
    if (i == 0) g_rptr[0] = 0;
    g_dinv[i] = rsqrtf((float)g_cnt[i] + 1.0f);
}

__global__ void k_fill(const int* __restrict__ src, const int* __restrict__ dst, int e) {
    int i = blockIdx.x * blockDim.x + threadIdx.x;
    if (i < e) {
        int d = dst[i];
        int pos = atomicAdd(&g_cursor[d], 1);
        g_col[pos] = src[i];
    }
}

// ---------------------------------------------------------------------------
// GEMM: H[n,128](fp16) = X'[n,128] @ W[128,128]
//   MODE 0: X' = X
//   MODE 1: X' = leakyrelu(X + bias_in)  (fuses previous layer's epilogue)
// BM=128, BN=128, BK=16, 256 threads, 8x8 per thread, register prefetch.
// ---------------------------------------------------------------------------
template <int MODE>
__global__ void __launch_bounds__(256)
k_gemm(const float* __restrict__ X, const float* __restrict__ W,
       const float* __restrict__ bias_in, __half2* __restrict__ H, int n)
{
    __shared__ float As[16][132];   // [k][m], padded
    __shared__ float Bs[16][128];   // [k][ncol]

    const int t  = threadIdx.x;
    const int tx = t & 15;          // 16 col-groups (8 cols each)
    const int ty = t >> 4;          // 16 row-groups (8 rows each)
    const int row0 = blockIdx.x * 128;

    // A: thread loads row ar, cols {ac..ac+3, ac+8..ac+11}
    const int ar = t >> 1;
    const int ac = (t & 1) << 2;    // 0 or 4
    // B: thread loads row bk, 8 consecutive cols
    const int bk = t >> 4;          // 0..15
    const int bc = (t & 15) << 3;   // 0..120

    float acc[8][8];
#pragma unroll
    for (int i = 0; i < 8; i++)
#pragma unroll
        for (int j = 0; j < 8; j++) acc[i][j] = 0.0f;

    const int rA = row0 + ar;
    const bool aok = (rA < n);
    const float* Arow = X + (size_t)rA * D;

    float4 pa0, pa1, pb0, pb1;

    auto load_tile = [&](int kt) {
        pa0 = make_float4(0.f, 0.f, 0.f, 0.f);
        pa1 = pa0;
        if (aok) {
            pa0 = *(const float4*)&Arow[kt + ac];
            pa1 = *(const float4*)&Arow[kt + ac + 8];
        }
        if (MODE == 1) {
            float4 b0 = *(const float4*)&bias_in[kt + ac];
            float4 b1 = *(const float4*)&bias_in[kt + ac + 8];
            pa0.x += b0.x; pa0.y += b0.y; pa0.z += b0.z; pa0.w += b0.w;
            pa1.x += b1.x; pa1.y += b1.y; pa1.z += b1.z; pa1.w += b1.w;
            pa0.x = fmaxf(pa0.x, NEG * pa0.x); pa0.y = fmaxf(pa0.y, NEG * pa0.y);
            pa0.z = fmaxf(pa0.z, NEG * pa0.z); pa0.w = fmaxf(pa0.w, NEG * pa0.w);
            pa1.x = fmaxf(pa1.x, NEG * pa1.x); pa1.y = fmaxf(pa1.y, NEG * pa1.y);
            pa1.z = fmaxf(pa1.z, NEG * pa1.z); pa1.w = fmaxf(pa1.w, NEG * pa1.w);
        }
        pb0 = *(const float4*)&W[(size_t)(kt + bk) * D + bc];
        pb1 = *(const float4*)&W[(size_t)(kt + bk) * D + bc + 4];
    };

    auto store_tile = [&]() {
        As[ac + 0][ar] = pa0.x; As[ac + 1][ar] = pa0.y;
        As[ac + 2][ar] = pa0.z; As[ac + 3][ar] = pa0.w;
        As[ac + 8][ar] = pa1.x; As[ac + 9][ar] = pa1.y;
        As[ac + 10][ar] = pa1.z; As[ac + 11][ar] = pa1.w;
        *(float4*)&Bs[bk][bc] = pb0;
        *(float4*)&Bs[bk][bc + 4] = pb1;
    };

    load_tile(0);
    store_tile();
    __syncthreads();

    for (int kt = 0; kt < D; kt += 16) {
        if (kt + 16 < D) load_tile(kt + 16);
#pragma unroll
        for (int k = 0; k < 16; k++) {
            float a[8], b[8];
            *(float4*)&a[0] = *(const float4*)&As[k][ty << 3];
            *(float4*)&a[4] = *(const float4*)&As[k][(ty << 3) + 4];
            *(float4*)&b[0] = *(const float4*)&Bs[k][tx << 3];
            *(float4*)&b[4] = *(const float4*)&Bs[k][(tx << 3) + 4];
#pragma unroll
            for (int i = 0; i < 8; i++)
#pragma unroll
                for (int j = 0; j < 8; j++)
                    acc[i][j] = fmaf(a[i], b[j], acc[i][j]);
        }
        if (kt + 16 < D) {
            __syncthreads();
            store_tile();
            __syncthreads();
        }
    }

    // epilogue: fp16 store (row = 64 half2)
#pragma unroll
    for (int i = 0; i < 8; i++) {
        int r = row0 + (ty << 3) + i;
        if (r < n) {
            __half2 h0 = __floats2half2_rn(acc[i][0], acc[i][1]);
            __half2 h1 = __floats2half2_rn(acc[i][2], acc[i][3]);
            __half2 h2 = __floats2half2_rn(acc[i][4], acc[i][5]);
            __half2 h3 = __floats2half2_rn(acc[i][6], acc[i][7]);
            uint4 u;
            u.x = *(unsigned*)&h0; u.y = *(unsigned*)&h1;
            u.z = *(unsigned*)&h2; u.w = *(unsigned*)&h3;
            *(uint4*)&H[(size_t)r * 64 + (tx << 2)] = u;
        }
    }
}

// ---------------------------------------------------------------------------
// Aggregation (CSR gather, fp16 H):
//   out[d] = H[d]*dinv[d]^2 + sum_{s in N(d)} H[s]*dinv[s]*dinv[d]
// One warp per dst node; lane owns 4 columns (one uint2 = 4 halfs per row).
//   MODE 0: write raw fp32   MODE 1: write leakyrelu(. + bias)
// ---------------------------------------------------------------------------
template <int MODE>
__global__ void __launch_bounds__(256)
k_agg(const __half2* __restrict__ H, const float* __restrict__ bias,
      float* __restrict__ out, int n)
{
    int node = (blockIdx.x * blockDim.x + threadIdx.x) >> 5;
    int lane = threadIdx.x & 31;
    if (node >= n) return;

    float dd = g_dinv[node];
    float d2 = dd * dd;

    uint2 u = *(const uint2*)(H + (size_t)node * 64 + (lane << 1));
    float2 f0 = __half22float2(*(__half2*)&u.x);
    float2 f1 = __half22float2(*(__half2*)&u.y);
    float4 acc = make_float4(f0.x * d2, f0.y * d2, f1.x * d2, f1.y * d2);

    int beg = g_rptr[node], end = g_rptr[node + 1];
    for (int j = beg; j < end; j += 32) {
        int idx = j + lane;
        int s = 0; float c = 0.0f;
        if (idx < end) { s = g_col[idx]; c = g_dinv[s] * dd; }
        int cnt = min(32, end - j);
        for (int t = 0; t < cnt; t++) {
            int   ss = __shfl_sync(0xffffffffu, s, t);
            float cc = __shfl_sync(0xffffffffu, c, t);
            uint2 hu = *(const uint2*)(H + (size_t)ss * 64 + (lane << 1));
            float2 h0 = __half22float2(*(__half2*)&hu.x);
            float2 h1 = __half22float2(*(__half2*)&hu.y);
            acc.x = fmaf(h0.x, cc, acc.x);
            acc.y = fmaf(h0.y, cc, acc.y);
            acc.z = fmaf(h1.x, cc, acc.z);
            acc.w = fmaf(h1.y, cc, acc.w);
        }
    }

    if (MODE == 1) {
        float4 b = *(const float4*)&bias[lane << 2];
        acc.x += b.x; acc.y += b.y; acc.z += b.z; acc.w += b.w;
        acc.x = fmaxf(acc.x, NEG * acc.x);
        acc.y = fmaxf(acc.y, NEG * acc.y);
        acc.z = fmaxf(acc.z, NEG * acc.z);
        acc.w = fmaxf(acc.w, NEG * acc.w);
    }
    *(float4*)&out[(size_t)node * D + (lane << 2)] = acc;
}

// ---------------------------------------------------------------------------
extern "C" void kernel_launch(void* const* d_in, const int* in_sizes, int n_in,
                              void* d_out, int out_size)
{
    const float* x  = (const float*)d_in[0];
    const float* W1 = (const float*)d_in[1];
    const float* b1 = (const float*)d_in[2];
    const float* W2 = (const float*)d_in[3];
    const float* b2 = (const float*)d_in[4];
    const int*   ei = (const int*)d_in[5];

    const int n = in_sizes[0] / D;
    const int e = in_sizes[5] / 2;
    const int* src = ei;
    const int* dst = ei + e;

    __half2* h;
    float* acc;
    cudaGetSymbolAddress((void**)&h,   g_h);
    cudaGetSymbolAddress((void**)&acc, g_acc);

    // degree + CSR build
    k_zero_cnt<<<(n + 255) / 256, 256>>>(n);
    k_count<<<(e + 255) / 256, 256>>>(dst, e);
    const int nb = (n + 1023) / 1024;
    k_scan_block<<<nb, 1024>>>(n);
    k_scan_sums<<<1, 32>>>(nb);
    k_finalize<<<(n + 255) / 256, 256>>>(n);
    k_fill<<<(e + 255) / 256, 256>>>(src, dst, e);

    const int gemm_blocks = (n + 127) / 128;
    const int agg_blocks  = (int)(((long long)n * 32 + 255) / 256);

    // layer 1
    k_gemm<0><<<gemm_blocks, 256>>>(x, W1, nullptr, h, n);
    k_agg<0><<<agg_blocks, 256>>>(h, nullptr, acc, n);

    // layer 2 (layer-1 bias+leakyrelu fused into GEMM A-load,
    //          layer-2 bias+leakyrelu fused into aggregation epilogue)
    k_gemm<1><<<gemm_blocks, 256>>>(acc, W2, b1, h, n);
    k_agg<1><<<agg_blocks, 256>>>(h, b2, (float*)d_out, n);
}

// round 4
// speedup vs baseline: 2.5768x; 1.3418x over previous
#include <cuda_runtime.h>
#include <cuda_fp16.h>

#define D 128
#define NEG 0.01f
#define NMAX 100000
#define EMAX 2000000
#define NBMAX 128   // scan blocks: ceil(NMAX/1024) = 98
#define LDS_PAD 8   // smem row pad (halfs) -> conflict-free ldmatrix
#define LDA (D + LDS_PAD)

// Scratch (allocation-free rule: __device__ globals)
__device__ __half2 g_h[NMAX * 64];     // H = X' @ W, fp16 (consumed by agg)
__device__ __half2 g_x2[NMAX * 64];    // layer-2 input, fp16 (agg1 output)
__device__ __half  g_w1h[D * D];       // W1 fp16
__device__ __half  g_w2h[D * D];       // W2 fp16
__device__ float g_dinv[NMAX];
__device__ int   g_cnt[NMAX];
__device__ int   g_rptr[NMAX + 1];
__device__ int   g_cursor[NMAX];
__device__ int   g_partial[NMAX];
__device__ int   g_bsum[NBMAX];
__device__ int   g_boff[NBMAX];
__device__ int   g_col[EMAX];

// ---------------------------------------------------------------------------
// Degree + CSR build
// ---------------------------------------------------------------------------
__global__ void k_zero_cnt(int n) {
    int i = blockIdx.x * blockDim.x + threadIdx.x;
    if (i < n) g_cnt[i] = 0;
}

__global__ void k_count(const int* __restrict__ dst, int e) {
    int i = blockIdx.x * blockDim.x + threadIdx.x;
    if (i < e) atomicAdd(&g_cnt[dst[i]], 1);
}

__global__ void __launch_bounds__(1024) k_scan_block(int n) {
    __shared__ int sh[1024];
    int i = blockIdx.x * 1024 + threadIdx.x;
    int v = (i < n) ? g_cnt[i] : 0;
    sh[threadIdx.x] = v;
#pragma unroll
    for (int off = 1; off < 1024; off <<= 1) {
        __syncthreads();
        int t = (threadIdx.x >= off) ? sh[threadIdx.x - off] : 0;
        __syncthreads();
        sh[threadIdx.x] += t;
    }
    if (i < n) g_partial[i] = sh[threadIdx.x];
    if (threadIdx.x == 1023) g_bsum[blockIdx.x] = sh[1023];
}

__global__ void k_scan_sums(int nb) {
    int t = threadIdx.x;            // 32 threads
    int b = t * 4;
    int s0 = (b + 0 < nb) ? g_bsum[b + 0] : 0;
    int s1 = (b + 1 < nb) ? g_bsum[b + 1] : 0;
    int s2 = (b + 2 < nb) ? g_bsum[b + 2] : 0;
    int s3 = (b + 3 < nb) ? g_bsum[b + 3] : 0;
    int tot = s0 + s1 + s2 + s3;
    int x = tot;
#pragma unroll
    for (int o = 1; o < 32; o <<= 1) {
        int y = __shfl_up_sync(0xffffffffu, x, o);
        if (t >= o) x += y;
    }
    int excl = x - tot;
    if (b + 0 < nb) g_boff[b + 0] = excl;
    if (b + 1 < nb) g_boff[b + 1] = excl + s0;
    if (b + 2 < nb) g_boff[b + 2] = excl + s0 + s1;
    if (b + 3 < nb) g_boff[b + 3] = excl + s0 + s1 + s2;
}

__global__ void k_finalize(int n) {
    int i = blockIdx.x * blockDim.x + threadIdx.x;
    if (i >= n) return;
    int incl = g_partial[i] + g_boff[i >> 10];
    g_rptr[i + 1] = incl;
    g_cursor[i] = incl - g_cnt[i];
    if (i == 0) g_rptr[0] = 0;
    g_dinv[i] = rsqrtf((float)g_cnt[i] + 1.0f);
}

__global__ void k_fill(const int* __restrict__ src, const int* __restrict__ dst, int e) {
    int i = blockIdx.x * blockDim.x + threadIdx.x;
    if (i < e) {
        int d = dst[i];
        int pos = atomicAdd(&g_cursor[d], 1);
        g_col[pos] = src[i];
    }
}

// convert both weight matrices to fp16
__global__ void k_convW(const float* __restrict__ W1, const float* __restrict__ W2) {
    int i = blockIdx.x * blockDim.x + threadIdx.x;   // D*D threads
    if (i < D * D) {
        g_w1h[i] = __float2half(W1[i]);
        g_w2h[i] = __float2half(W2[i]);
    }
}

// ---------------------------------------------------------------------------
// Tensor-core GEMM: H[n,128](fp16) = X[n,128] @ W[128,128]
// A: fp32 (layer1) or fp16 (layer2). BM=128, full N=K=128 per block.
// 8 warps, warp w owns rows [16w,16w+16): mma.m16n8k16, fp32 accum.
// ---------------------------------------------------------------------------
template <typename TA>
__global__ void __launch_bounds__(256)
k_gemm_tc(const TA* __restrict__ X, const __half* __restrict__ Wh,
          __half2* __restrict__ H, int n)
{
    extern __shared__ __half sm[];
    __half* As = sm;                 // [128][LDA]
    __half* Ws = sm + 128 * LDA;     // [128][LDA]

    const int t    = threadIdx.x;
    const int wid  = t >> 5;
    const int lane = t & 31;
    const int row0 = blockIdx.x * 128;

    // ---- load W tile (fp16 global -> smem), 64 halfs per thread
    {
        int wr = t >> 1;
        int wc = (t & 1) << 6;       // 0 or 64
#pragma unroll
        for (int j = 0; j < 8; j++) {
            uint4 u = *(const uint4*)&Wh[wr * D + wc + j * 8];
            *(uint4*)&Ws[wr * LDA + wc + j * 8] = u;
        }
    }
    // ---- load A tile (convert fp32 -> fp16 if needed)
    {
        int ar = t >> 1;
        int ac = (t & 1) << 6;
        int r = row0 + ar;
        if (r < n) {
            if constexpr (sizeof(TA) == 4) {
                const float* Xr = (const float*)X + (size_t)r * D + ac;
#pragma unroll
                for (int j = 0; j < 8; j++) {
                    float4 f0 = *(const float4*)&Xr[j * 8];
                    float4 f1 = *(const float4*)&Xr[j * 8 + 4];
                    __half2 h0 = __floats2half2_rn(f0.x, f0.y);
                    __half2 h1 = __floats2half2_rn(f0.z, f0.w);
                    __half2 h2 = __floats2half2_rn(f1.x, f1.y);
                    __half2 h3 = __floats2half2_rn(f1.z, f1.w);
                    uint4 u;
                    u.x = *(unsigned*)&h0; u.y = *(unsigned*)&h1;
                    u.z = *(unsigned*)&h2; u.w = *(unsigned*)&h3;
                    *(uint4*)&As[ar * LDA + ac + j * 8] = u;
                }
            } else {
                const __half* Xr = (const __half*)X + (size_t)r * D + ac;
#pragma unroll
                for (int j = 0; j < 8; j++)
                    *(uint4*)&As[ar * LDA + ac + j * 8] = *(const uint4*)&Xr[j * 8];
            }
        } else {
            uint4 z = make_uint4(0, 0, 0, 0);
#pragma unroll
            for (int j = 0; j < 8; j++)
                *(uint4*)&As[ar * LDA + ac + j * 8] = z;
        }
    }
    __syncthreads();

    // ---- MMA: warp computes rows [16*wid, 16*wid+16) x all 128 cols
    float acc[16][4];
#pragma unroll
    for (int i = 0; i < 16; i++)
#pragma unroll
        for (int j = 0; j < 4; j++) acc[i][j] = 0.0f;

    const int m0 = wid << 4;
    // A ldmatrix address: row m0 + lane%16, col half (lane/16)*8 within k-chunk
    const __half* a_base = As + (m0 + (lane & 15)) * LDA + ((lane >> 4) << 3);
    // B ldmatrix address: row k0 + lane%16, col n0 + (lane/16)*8
    const __half* b_base = Ws + (lane & 15) * LDA + ((lane >> 4) << 3);

#pragma unroll
    for (int ks = 0; ks < 8; ks++) {
        unsigned a0, a1, a2, a3;
        {
            unsigned sa = (unsigned)__cvta_generic_to_shared(a_base + ks * 16);
            asm volatile("ldmatrix.sync.aligned.m8n8.x4.shared.b16 {%0,%1,%2,%3}, [%4];"
                         : "=r"(a0), "=r"(a1), "=r"(a2), "=r"(a3) : "r"(sa));
        }
#pragma unroll
        for (int nc = 0; nc < 8; nc++) {
            unsigned b0, b1, b2, b3;
            unsigned sb = (unsigned)__cvta_generic_to_shared(
                b_base + (ks * 16) * LDA + nc * 16);
            asm volatile("ldmatrix.sync.aligned.m8n8.x4.trans.shared.b16 {%0,%1,%2,%3}, [%4];"
                         : "=r"(b0), "=r"(b1), "=r"(b2), "=r"(b3) : "r"(sb));
            float* c = acc[2 * nc];
            asm volatile("mma.sync.aligned.m16n8k16.row.col.f32.f16.f16.f32 "
                         "{%0,%1,%2,%3}, {%4,%5,%6,%7}, {%8,%9}, {%0,%1,%2,%3};"
                         : "+f"(c[0]), "+f"(c[1]), "+f"(c[2]), "+f"(c[3])
                         : "r"(a0), "r"(a1), "r"(a2), "r"(a3), "r"(b0), "r"(b1));
            float* c2 = acc[2 * nc + 1];
            asm volatile("mma.sync.aligned.m16n8k16.row.col.f32.f16.f16.f32 "
                         "{%0,%1,%2,%3}, {%4,%5,%6,%7}, {%8,%9}, {%0,%1,%2,%3};"
                         : "+f"(c2[0]), "+f"(c2[1]), "+f"(c2[2]), "+f"(c2[3])
                         : "r"(a0), "r"(a1), "r"(a2), "r"(a3), "r"(b2), "r"(b3));
        }
    }

    // ---- epilogue: fp16 store. c-frag: rows (lane/4, lane/4+8), cols (lane%4)*2
    __half* Hp = (__half*)H;
    const int r0 = row0 + m0 + (lane >> 2);
    const int cb = (lane & 3) << 1;
#pragma unroll
    for (int nc = 0; nc < 8; nc++) {
#pragma unroll
        for (int half8 = 0; half8 < 2; half8++) {
            float* c = acc[2 * nc + half8];
            int col = nc * 16 + half8 * 8 + cb;
            if (r0 < n) {
                __half2 v = __floats2half2_rn(c[0], c[1]);
                *(unsigned*)&Hp[(size_t)r0 * D + col] = *(unsigned*)&v;
            }
            if (r0 + 8 < n) {
                __half2 v = __floats2half2_rn(c[2], c[3]);
                *(unsigned*)&Hp[(size_t)(r0 + 8) * D + col] = *(unsigned*)&v;
            }
        }
    }
}

// ---------------------------------------------------------------------------
// Aggregation (CSR gather, fp16 H):
//   t[d] = H[d]*dinv[d]^2 + sum_{s in N(d)} H[s]*dinv[s]*dinv[d]
//   out = leakyrelu(t + bias);  OUTHALF: fp16 (layer1) or fp32 (layer2/d_out)
// One warp per dst node; lane owns 4 columns.
// ---------------------------------------------------------------------------
template <int OUTHALF>
__global__ void __launch_bounds__(256)
k_agg(const __half2* __restrict__ H, const float* __restrict__ bias,
      void* __restrict__ outp, int n)
{
    int node = (blockIdx.x * blockDim.x + threadIdx.x) >> 5;
    int lane = threadIdx.x & 31;
    if (node >= n) return;

    float dd = g_dinv[node];
    float d2 = dd * dd;

    uint2 u = *(const uint2*)(H + (size_t)node * 64 + (lane << 1));
    float2 f0 = __half22float2(*(__half2*)&u.x);
    float2 f1 = __half22float2(*(__half2*)&u.y);
    float4 acc = make_float4(f0.x * d2, f0.y * d2, f1.x * d2, f1.y * d2);

    int beg = g_rptr[node], end = g_rptr[node + 1];
    for (int j = beg; j < end; j += 32) {
        int idx = j + lane;
        int s = 0; float c = 0.0f;
        if (idx < end) { s = g_col[idx]; c = g_dinv[s] * dd; }
        int cnt = min(32, end - j);
        for (int t = 0; t < cnt; t++) {
            int   ss = __shfl_sync(0xffffffffu, s, t);
            float cc = __shfl_sync(0xffffffffu, c, t);
            uint2 hu = *(const uint2*)(H + (size_t)ss * 64 + (lane << 1));
            float2 h0 = __half22float2(*(__half2*)&hu.x);
            float2 h1 = __half22float2(*(__half2*)&hu.y);
            acc.x = fmaf(h0.x, cc, acc.x);
            acc.y = fmaf(h0.y, cc, acc.y);
            acc.z = fmaf(h1.x, cc, acc.z);
            acc.w = fmaf(h1.y, cc, acc.w);
        }
    }

    float4 b = *(const float4*)&bias[lane << 2];
    acc.x += b.x; acc.y += b.y; acc.z += b.z; acc.w += b.w;
    acc.x = fmaxf(acc.x, NEG * acc.x);
    acc.y = fmaxf(acc.y, NEG * acc.y);
    acc.z = fmaxf(acc.z, NEG * acc.z);
    acc.w = fmaxf(acc.w, NEG * acc.w);

    if (OUTHALF) {
        __half2 h0 = __floats2half2_rn(acc.x, acc.y);
        __half2 h1 = __floats2half2_rn(acc.z, acc.w);
        uint2 o; o.x = *(unsigned*)&h0; o.y = *(unsigned*)&h1;
        *(uint2*)((__half2*)outp + (size_t)node * 64 + (lane << 1)) = o;
    } else {
        *(float4*)((float*)outp + (size_t)node * D + (lane << 2)) = acc;
    }
}

// ---------------------------------------------------------------------------
extern "C" void kernel_launch(void* const* d_in, const int* in_sizes, int n_in,
                              void* d_out, int out_size)
{
    const float* x  = (const float*)d_in[0];
    const float* W1 = (const float*)d_in[1];
    const float* b1 = (const float*)d_in[2];
    const float* W2 = (const float*)d_in[3];
    const float* b2 = (const float*)d_in[4];
    const int*   ei = (const int*)d_in[5];

    const int n = in_sizes[0] / D;
    const int e = in_sizes[5] / 2;
    const int* src = ei;
    const int* dst = ei + e;

    __half2 *h, *x2;
    __half *w1h, *w2h;
    cudaGetSymbolAddress((void**)&h,   g_h);
    cudaGetSymbolAddress((void**)&x2,  g_x2);
    cudaGetSymbolAddress((void**)&w1h, g_w1h);
    cudaGetSymbolAddress((void**)&w2h, g_w2h);

    const int smem = 2 * 128 * LDA * (int)sizeof(__half);
    static int attr_set = 0;  // host-side idempotent attribute set (not device state)
    if (!attr_set) {
        cudaFuncSetAttribute(k_gemm_tc<float>,
                             cudaFuncAttributeMaxDynamicSharedMemorySize, smem);
        cudaFuncSetAttribute(k_gemm_tc<__half>,
                             cudaFuncAttributeMaxDynamicSharedMemorySize, smem);
        attr_set = 1;
    }

    // degree + CSR build + weight conversion
    k_zero_cnt<<<(n + 255) / 256, 256>>>(n);
    k_count<<<(e + 255) / 256, 256>>>(dst, e);
    const int nb = (n + 1023) / 1024;
    k_scan_block<<<nb, 1024>>>(n);
    k_scan_sums<<<1, 32>>>(nb);
    k_finalize<<<(n + 255) / 256, 256>>>(n);
    k_fill<<<(e + 255) / 256, 256>>>(src, dst, e);
    k_convW<<<(D * D + 255) / 256, 256>>>(W1, W2);

    const int gemm_blocks = (n + 127) / 128;
    const int agg_blocks  = (int)(((long long)n * 32 + 255) / 256);

    // layer 1: H = x@W1 ; x2 = fp16(leakyrelu(agg(H) + b1))
    k_gemm_tc<float><<<gemm_blocks, 256, smem>>>(x, w1h, h, n);
    k_agg<1><<<agg_blocks, 256>>>(h, b1, x2, n);

    // layer 2: H = x2@W2 ; out = leakyrelu(agg(H) + b2)
    k_gemm_tc<__half><<<gemm_blocks, 256, smem>>>((const __half*)x2, w2h, h, n);
    k_agg<0><<<agg_blocks, 256>>>(h, b2, d_out, n);
}

// round 5
// speedup vs baseline: 3.0525x; 1.1846x over previous
#include <cuda_runtime.h>
#include <cuda_fp16.h>

#define D 128
#define NEG 0.01f
#define NMAX 100000
#define EMAX 2000000
#define NBMAX 128   // scan blocks: ceil(NMAX/1024) = 98
#define LDS_PAD 8
#define LDA (D + LDS_PAD)

// Scratch (allocation-free rule: __device__ globals)
__device__ __half2 g_h[NMAX * 64];     // H' = (X' @ W) * dinv_row, fp16
__device__ __half2 g_x2[NMAX * 64];    // layer-2 input, fp16
__device__ __half  g_w1h[D * D];
__device__ __half  g_w2h[D * D];
__device__ float g_dinv[NMAX];
__device__ int   g_cnt[NMAX];
__device__ int   g_rptr[NMAX + 1];
__device__ int   g_cursor[NMAX];
__device__ int   g_partial[NMAX];
__device__ int   g_bsum[NBMAX];

// ---------------------------------------------------------------------------
// Setup: zero degree counters + convert both weight matrices to fp16
// ---------------------------------------------------------------------------
__global__ void k_setup(const float* __restrict__ W1, const float* __restrict__ W2, int n) {
    int i = blockIdx.x * blockDim.x + threadIdx.x;
    if (i < n) g_cnt[i] = 0;
    if (i < D * D) {
        g_w1h[i] = __float2half(W1[i]);
        g_w2h[i] = __float2half(W2[i]);
    }
}

__global__ void k_count(const int* __restrict__ dst, int e) {
    int i = blockIdx.x * blockDim.x + threadIdx.x;
    if (i < e) atomicAdd(&g_cnt[dst[i]], 1);
}

// block-wise inclusive scan of g_cnt + dinv computation
__global__ void __launch_bounds__(1024) k_scan_block(int n) {
    __shared__ int sh[1024];
    int i = blockIdx.x * 1024 + threadIdx.x;
    int v = (i < n) ? g_cnt[i] : 0;
    if (i < n) g_dinv[i] = rsqrtf((float)v + 1.0f);
    sh[threadIdx.x] = v;
#pragma unroll
    for (int off = 1; off < 1024; off <<= 1) {
        __syncthreads();
        int t = (threadIdx.x >= off) ? sh[threadIdx.x - off] : 0;
        __syncthreads();
        sh[threadIdx.x] += t;
    }
    if (i < n) g_partial[i] = sh[threadIdx.x];
    if (threadIdx.x == 1023) g_bsum[blockIdx.x] = sh[1023];
}

// finalize rptr/cursor; block-sum scan done redundantly per block (warp 0)
__global__ void __launch_bounds__(256) k_finalize(int n, int nb) {
    __shared__ int boff_s[NBMAX];
    if (threadIdx.x < 32) {
        int t = threadIdx.x;
        int b = t * 4;
        int s0 = (b + 0 < nb) ? g_bsum[b + 0] : 0;
        int s1 = (b + 1 < nb) ? g_bsum[b + 1] : 0;
        int s2 = (b + 2 < nb) ? g_bsum[b + 2] : 0;
        int s3 = (b + 3 < nb) ? g_bsum[b + 3] : 0;
        int tot = s0 + s1 + s2 + s3;
        int x = tot;
#pragma unroll
        for (int o = 1; o < 32; o <<= 1) {
            int y = __shfl_up_sync(0xffffffffu, x, o);
            if (t >= o) x += y;
        }
        int excl = x - tot;
        if (b + 0 < NBMAX) boff_s[b + 0] = excl;
        if (b + 1 < NBMAX) boff_s[b + 1] = excl + s0;
        if (b + 2 < NBMAX) boff_s[b + 2] = excl + s0 + s1;
        if (b + 3 < NBMAX) boff_s[b + 3] = excl + s0 + s1 + s2;
    }
    __syncthreads();
    int i = blockIdx.x * blockDim.x + threadIdx.x;
    if (i >= n) return;
    int incl = g_partial[i] + boff_s[i >> 10];
    g_rptr[i + 1] = incl;
    g_cursor[i] = incl - g_cnt[i];
    if (i == 0) g_rptr[0] = 0;
}

__device__ int g_col[EMAX];

__global__ void k_fill(const int* __restrict__ src, const int* __restrict__ dst, int e) {
    int i = blockIdx.x * blockDim.x + threadIdx.x;
    if (i < e) {
        int d = dst[i];
        int pos = atomicAdd(&g_cursor[d], 1);
        g_col[pos] = src[i];
    }
}

// ---------------------------------------------------------------------------
// Tensor-core GEMM: H'[n,128](fp16) = (X[n,128] @ W[128,128]) * dinv[row]
// ---------------------------------------------------------------------------
template <typename TA>
__global__ void __launch_bounds__(256)
k_gemm_tc(const TA* __restrict__ X, const __half* __restrict__ Wh,
          __half2* __restrict__ H, int n)
{
    extern __shared__ __half sm[];
    __half* As = sm;
    __half* Ws = sm + 128 * LDA;

    const int t    = threadIdx.x;
    const int wid  = t >> 5;
    const int lane = t & 31;
    const int row0 = blockIdx.x * 128;

    {   // W tile
        int wr = t >> 1;
        int wc = (t & 1) << 6;
#pragma unroll
        for (int j = 0; j < 8; j++) {
            uint4 u = *(const uint4*)&Wh[wr * D + wc + j * 8];
            *(uint4*)&Ws[wr * LDA + wc + j * 8] = u;
        }
    }
    {   // A tile
        int ar = t >> 1;
        int ac = (t & 1) << 6;
        int r = row0 + ar;
        if (r < n) {
            if constexpr (sizeof(TA) == 4) {
                const float* Xr = (const float*)X + (size_t)r * D + ac;
#pragma unroll
                for (int j = 0; j < 8; j++) {
                    float4 f0 = *(const float4*)&Xr[j * 8];
                    float4 f1 = *(const float4*)&Xr[j * 8 + 4];
                    __half2 h0 = __floats2half2_rn(f0.x, f0.y);
                    __half2 h1 = __floats2half2_rn(f0.z, f0.w);
                    __half2 h2 = __floats2half2_rn(f1.x, f1.y);
                    __half2 h3 = __floats2half2_rn(f1.z, f1.w);
                    uint4 u;
                    u.x = *(unsigned*)&h0; u.y = *(unsigned*)&h1;
                    u.z = *(unsigned*)&h2; u.w = *(unsigned*)&h3;
                    *(uint4*)&As[ar * LDA + ac + j * 8] = u;
                }
            } else {
                const __half* Xr = (const __half*)X + (size_t)r * D + ac;
#pragma unroll
                for (int j = 0; j < 8; j++)
                    *(uint4*)&As[ar * LDA + ac + j * 8] = *(const uint4*)&Xr[j * 8];
            }
        } else {
            uint4 z = make_uint4(0, 0, 0, 0);
#pragma unroll
            for (int j = 0; j < 8; j++)
                *(uint4*)&As[ar * LDA + ac + j * 8] = z;
        }
    }
    __syncthreads();

    float acc[16][4];
#pragma unroll
    for (int i = 0; i < 16; i++)
#pragma unroll
        for (int j = 0; j < 4; j++) acc[i][j] = 0.0f;

    const int m0 = wid << 4;
    const __half* a_base = As + (m0 + (lane & 15)) * LDA + ((lane >> 4) << 3);
    const __half* b_base = Ws + (lane & 15) * LDA + ((lane >> 4) << 3);

#pragma unroll
    for (int ks = 0; ks < 8; ks++) {
        unsigned a0, a1, a2, a3;
        {
            unsigned sa = (unsigned)__cvta_generic_to_shared(a_base + ks * 16);
            asm volatile("ldmatrix.sync.aligned.m8n8.x4.shared.b16 {%0,%1,%2,%3}, [%4];"
                         : "=r"(a0), "=r"(a1), "=r"(a2), "=r"(a3) : "r"(sa));
        }
#pragma unroll
        for (int nc = 0; nc < 8; nc++) {
            unsigned b0, b1, b2, b3;
            unsigned sb = (unsigned)__cvta_generic_to_shared(
                b_base + (ks * 16) * LDA + nc * 16);
            asm volatile("ldmatrix.sync.aligned.m8n8.x4.trans.shared.b16 {%0,%1,%2,%3}, [%4];"
                         : "=r"(b0), "=r"(b1), "=r"(b2), "=r"(b3) : "r"(sb));
            float* c = acc[2 * nc];
            asm volatile("mma.sync.aligned.m16n8k16.row.col.f32.f16.f16.f32 "
                         "{%0,%1,%2,%3}, {%4,%5,%6,%7}, {%8,%9}, {%0,%1,%2,%3};"
                         : "+f"(c[0]), "+f"(c[1]), "+f"(c[2]), "+f"(c[3])
                         : "r"(a0), "r"(a1), "r"(a2), "r"(a3), "r"(b0), "r"(b1));
            float* c2 = acc[2 * nc + 1];
            asm volatile("mma.sync.aligned.m16n8k16.row.col.f32.f16.f16.f32 "
                         "{%0,%1,%2,%3}, {%4,%5,%6,%7}, {%8,%9}, {%0,%1,%2,%3};"
                         : "+f"(c2[0]), "+f"(c2[1]), "+f"(c2[2]), "+f"(c2[3])
                         : "r"(a0), "r"(a1), "r"(a2), "r"(a3), "r"(b2), "r"(b3));
        }
    }

    // epilogue: prescale by dinv[row], store fp16
    __half* Hp = (__half*)H;
    const int r0 = row0 + m0 + (lane >> 2);
    const int cb = (lane & 3) << 1;
    const float d0 = (r0 < n)     ? g_dinv[r0]     : 0.0f;
    const float d1 = (r0 + 8 < n) ? g_dinv[r0 + 8] : 0.0f;
#pragma unroll
    for (int nc = 0; nc < 8; nc++) {
#pragma unroll
        for (int half8 = 0; half8 < 2; half8++) {
            float* c = acc[2 * nc + half8];
            int col = nc * 16 + half8 * 8 + cb;
            if (r0 < n) {
                __half2 v = __floats2half2_rn(c[0] * d0, c[1] * d0);
                *(unsigned*)&Hp[(size_t)r0 * D + col] = *(unsigned*)&v;
            }
            if (r0 + 8 < n) {
                __half2 v = __floats2half2_rn(c[2] * d1, c[3] * d1);
                *(unsigned*)&Hp[(size_t)(r0 + 8) * D + col] = *(unsigned*)&v;
            }
        }
    }
}

// ---------------------------------------------------------------------------
// Aggregation (CSR gather, prescaled fp16 H'):
//   out[d] = leakyrelu( dinv_d * (H'[d] + sum_{s in N(d)} H'[s]) + bias )
// One warp per dst node; lane owns 4 columns (uint2 = 4 halfs).
// ---------------------------------------------------------------------------
template <int OUTHALF>
__global__ void __launch_bounds__(256)
k_agg(const __half2* __restrict__ H, const float* __restrict__ bias,
      void* __restrict__ outp, int n)
{
    int node = (blockIdx.x * blockDim.x + threadIdx.x) >> 5;
    int lane = threadIdx.x & 31;
    if (node >= n) return;

    uint2 u = *(const uint2*)(H + (size_t)node * 64 + (lane << 1));
    float2 f0 = __half22float2(*(__half2*)&u.x);
    float2 f1 = __half22float2(*(__half2*)&u.y);
    float4 acc = make_float4(f0.x, f0.y, f1.x, f1.y);   // self term H'[d]

    int beg = g_rptr[node], end = g_rptr[node + 1];
    for (int j = beg; j < end; j += 32) {
        int idx = j + lane;
        int s = (idx < end) ? g_col[idx] : 0;
        int cnt = min(32, end - j);
        for (int t = 0; t < cnt; t++) {
            int ss = __shfl_sync(0xffffffffu, s, t);
            uint2 hu = *(const uint2*)(H + (size_t)ss * 64 + (lane << 1));
            float2 h0 = __half22float2(*(__half2*)&hu.x);
            float2 h1 = __half22float2(*(__half2*)&hu.y);
            acc.x += h0.x; acc.y += h0.y;
            acc.z += h1.x; acc.w += h1.y;
        }
    }

    float dd = g_dinv[node];
    float4 b = *(const float4*)&bias[lane << 2];
    acc.x = fmaf(acc.x, dd, b.x);
    acc.y = fmaf(acc.y, dd, b.y);
    acc.z = fmaf(acc.z, dd, b.z);
    acc.w = fmaf(acc.w, dd, b.w);
    acc.x = fmaxf(acc.x, NEG * acc.x);
    acc.y = fmaxf(acc.y, NEG * acc.y);
    acc.z = fmaxf(acc.z, NEG * acc.z);
    acc.w = fmaxf(acc.w, NEG * acc.w);

    if (OUTHALF) {
        __half2 h0 = __floats2half2_rn(acc.x, acc.y);
        __half2 h1 = __floats2half2_rn(acc.z, acc.w);
        uint2 o; o.x = *(unsigned*)&h0; o.y = *(unsigned*)&h1;
        *(uint2*)((__half2*)outp + (size_t)node * 64 + (lane << 1)) = o;
    } else {
        *(float4*)((float*)outp + (size_t)node * D + (lane << 2)) = acc;
    }
}

// ---------------------------------------------------------------------------
extern "C" void kernel_launch(void* const* d_in, const int* in_sizes, int n_in,
                              void* d_out, int out_size)
{
    const float* x  = (const float*)d_in[0];
    const float* W1 = (const float*)d_in[1];
    const float* b1 = (const float*)d_in[2];
    const float* W2 = (const float*)d_in[3];
    const float* b2 = (const float*)d_in[4];
    const int*   ei = (const int*)d_in[5];

    const int n = in_sizes[0] / D;
    const int e = in_sizes[5] / 2;
    const int* src = ei;
    const int* dst = ei + e;

    __half2 *h, *x2;
    __half *w1h, *w2h;
    cudaGetSymbolAddress((void**)&h,   g_h);
    cudaGetSymbolAddress((void**)&x2,  g_x2);
    cudaGetSymbolAddress((void**)&w1h, g_w1h);
    cudaGetSymbolAddress((void**)&w2h, g_w2h);

    const int smem = 2 * 128 * LDA * (int)sizeof(__half);
    static cudaStream_t s2 = nullptr;
    static cudaEvent_t ev1 = nullptr, ev2 = nullptr;
    if (!s2) {  // one-time handle/attr setup (host resources, not device state)
        cudaFuncSetAttribute(k_gemm_tc<float>,
                             cudaFuncAttributeMaxDynamicSharedMemorySize, smem);
        cudaFuncSetAttribute(k_gemm_tc<__half>,
                             cudaFuncAttributeMaxDynamicSharedMemorySize, smem);
        cudaStreamCreateWithFlags(&s2, cudaStreamNonBlocking);
        cudaEventCreateWithFlags(&ev1, cudaEventDisableTiming);
        cudaEventCreateWithFlags(&ev2, cudaEventDisableTiming);
    }

    const int gemm_blocks = (n + 127) / 128;
    const int agg_blocks  = (int)(((long long)n * 32 + 255) / 256);
    const int nb = (n + 1023) / 1024;

    // setup + degree (dinv ready after scan_block)
    k_setup<<<(n + 255) / 256, 256>>>(W1, W2, n);
    k_count<<<(e + 255) / 256, 256>>>(dst, e);
    k_scan_block<<<nb, 1024>>>(n);

    // fork: GEMM1 on side stream, CSR finalize+fill on main stream
    cudaEventRecord(ev1, 0);
    cudaStreamWaitEvent(s2, ev1, 0);
    k_gemm_tc<float><<<gemm_blocks, 256, smem, s2>>>(x, w1h, h, n);
    cudaEventRecord(ev2, s2);

    k_finalize<<<(n + 255) / 256, 256>>>(n, nb);
    k_fill<<<(e + 255) / 256, 256>>>(src, dst, e);
    cudaStreamWaitEvent(0, ev2, 0);

    // layer 1 aggregation -> fp16 x2
    k_agg<1><<<agg_blocks, 256>>>(h, b1, x2, n);

    // layer 2
    k_gemm_tc<__half><<<gemm_blocks, 256, smem>>>((const __half*)x2, w2h, h, n);
    k_agg<0><<<agg_blocks, 256>>>(h, b2, d_out, n);
}